// round 2
// baseline (speedup 1.0000x reference)
#include <cuda_runtime.h>
#include <math.h>

#define T_DIM 1024
#define B_DIM 64
#define D_DIM 512
#define N_DIM 64
#define BN_ (B_DIM * N_DIM)          /* 4096 */
#define TBN_ (T_DIM * BN_)           /* 4,194,304 */

// Scratch (padded by one timestep so the scan's t+1 prefetch never branches)
__device__ float g_k [TBN_ + BN_];
__device__ float g_q [TBN_ + BN_];
__device__ float g_e [TBN_ + BN_];
__device__ float g_wv[TBN_ + BN_];

__device__ __forceinline__ float sigmoidf_(float x) {
    return 1.0f / (1.0f + __expf(-x));
}

// ---------------------------------------------------------------------------
// Gate kernel: grid (T, 4), block 256.
//  g=0: k = softmax(x W_k^T)    g=1: q = softmax(x W_q^T)
//  g=2: e = sigmoid(x W_e^T)    g=3: wv = sigmoid(x W_w^T) * (x W_v^T)
// Each CTA: one t (64 batch rows) x 64 cols, K=512, BK=32, 4x4 microtile.
// ---------------------------------------------------------------------------
__global__ __launch_bounds__(256, 1) void gates_kernel(
    const float* __restrict__ x,
    const float* __restrict__ Wk, const float* __restrict__ Wv,
    const float* __restrict__ Wq, const float* __restrict__ We,
    const float* __restrict__ Ww)
{
    __shared__ float sm[6144];          // As[2048] | Ws[2048] | Ws2[2048]
    float* As  = sm;
    float* Ws  = sm + 2048;
    float* Ws2 = sm + 4096;

    const int t   = blockIdx.x;
    const int g   = blockIdx.y;
    const int tid = threadIdx.x;
    const int tr  = tid >> 4;           // 0..15 (row group of 4 b-rows)
    const int tc  = tid & 15;           // 0..15 (col group of 4 n-cols)

    const float* W1 = (g == 0) ? Wk : (g == 1) ? Wq : (g == 2) ? We : Ww;
    const float* W2 = Wv;

    float acc1[4][4];
    float acc2[4][4];
    #pragma unroll
    for (int i = 0; i < 4; i++)
        #pragma unroll
        for (int j = 0; j < 4; j++) { acc1[i][j] = 0.f; acc2[i][j] = 0.f; }

    const float* xt = x + (size_t)t * (B_DIM * D_DIM);

    for (int kt = 0; kt < D_DIM / 32; kt++) {
        const int d0 = kt * 32;
        __syncthreads();
        #pragma unroll
        for (int l = 0; l < 2; l++) {
            const int idx = tid + l * 256;      // 512 float4s total
            const int row = idx >> 3;           // 0..63
            const int c4  = idx & 7;            // 0..7
            const int dd  = d0 + c4 * 4;
            float4 vx = *(const float4*)(xt + row * D_DIM + dd);
            As[(c4 * 4 + 0) * 64 + row] = vx.x;
            As[(c4 * 4 + 1) * 64 + row] = vx.y;
            As[(c4 * 4 + 2) * 64 + row] = vx.z;
            As[(c4 * 4 + 3) * 64 + row] = vx.w;
            float4 vw = *(const float4*)(W1 + row * D_DIM + dd);
            Ws[(c4 * 4 + 0) * 64 + row] = vw.x;
            Ws[(c4 * 4 + 1) * 64 + row] = vw.y;
            Ws[(c4 * 4 + 2) * 64 + row] = vw.z;
            Ws[(c4 * 4 + 3) * 64 + row] = vw.w;
            if (g == 3) {
                float4 v2 = *(const float4*)(W2 + row * D_DIM + dd);
                Ws2[(c4 * 4 + 0) * 64 + row] = v2.x;
                Ws2[(c4 * 4 + 1) * 64 + row] = v2.y;
                Ws2[(c4 * 4 + 2) * 64 + row] = v2.z;
                Ws2[(c4 * 4 + 3) * 64 + row] = v2.w;
            }
        }
        __syncthreads();

        #pragma unroll
        for (int kk = 0; kk < 32; kk++) {
            float4 a  = *(const float4*)(As + kk * 64 + tr * 4);
            float4 b1 = *(const float4*)(Ws + kk * 64 + tc * 4);
            const float av[4] = {a.x, a.y, a.z, a.w};
            const float bv[4] = {b1.x, b1.y, b1.z, b1.w};
            #pragma unroll
            for (int i = 0; i < 4; i++)
                #pragma unroll
                for (int j = 0; j < 4; j++)
                    acc1[i][j] = fmaf(av[i], bv[j], acc1[i][j]);
            if (g == 3) {
                float4 b2 = *(const float4*)(Ws2 + kk * 64 + tc * 4);
                const float b2v[4] = {b2.x, b2.y, b2.z, b2.w};
                #pragma unroll
                for (int i = 0; i < 4; i++)
                    #pragma unroll
                    for (int j = 0; j < 4; j++)
                        acc2[i][j] = fmaf(av[i], b2v[j], acc2[i][j]);
            }
        }
    }

    const size_t obase = (size_t)t * BN_;

    if (g == 2) {
        #pragma unroll
        for (int i = 0; i < 4; i++)
            #pragma unroll
            for (int j = 0; j < 4; j++)
                g_e[obase + (tr * 4 + i) * 64 + (tc * 4 + j)] = sigmoidf_(acc1[i][j]);
    } else if (g == 3) {
        #pragma unroll
        for (int i = 0; i < 4; i++)
            #pragma unroll
            for (int j = 0; j < 4; j++)
                g_wv[obase + (tr * 4 + i) * 64 + (tc * 4 + j)] =
                    sigmoidf_(acc1[i][j]) * acc2[i][j];
    } else {
        // row-wise softmax over 64 logits, fused in-CTA
        float* Ls = sm;                  // reuse (4096 floats)
        __syncthreads();                 // done reading As/Ws
        #pragma unroll
        for (int i = 0; i < 4; i++)
            #pragma unroll
            for (int j = 0; j < 4; j++)
                Ls[(tr * 4 + i) * 64 + (tc * 4 + j)] = acc1[i][j];
        __syncthreads();

        const int r = tid >> 2;          // 0..63 (batch row)
        const int p = tid & 3;           // 4 lanes per row, 16 vals each
        float v[16];
        const float* rowp = Ls + r * 64 + p * 16;
        #pragma unroll
        for (int c = 0; c < 16; c++) v[c] = rowp[c];

        float m = v[0];
        #pragma unroll
        for (int c = 1; c < 16; c++) m = fmaxf(m, v[c]);
        m = fmaxf(m, __shfl_xor_sync(0xffffffffu, m, 1));
        m = fmaxf(m, __shfl_xor_sync(0xffffffffu, m, 2));

        float s = 0.f;
        #pragma unroll
        for (int c = 0; c < 16; c++) { v[c] = __expf(v[c] - m); s += v[c]; }
        s += __shfl_xor_sync(0xffffffffu, s, 1);
        s += __shfl_xor_sync(0xffffffffu, s, 2);
        const float inv = 1.0f / s;

        float* dst = ((g == 0) ? g_k : g_q) + obase + r * 64 + p * 16;
        #pragma unroll
        for (int c = 0; c < 16; c++) dst[c] = v[c] * inv;
    }
}

// ---------------------------------------------------------------------------
// Scan kernel: grid (4 rowgroups, 64 batches), block 128.
// thread -> (row_local = tid>>3, colgroup = tid&7): owns S[row, cg*8 .. cg*8+7]
// Recurrence per step: S = S + k_j * (wv_i - e_i * S); out_i = tanh(S . q)
// ---------------------------------------------------------------------------
__global__ __launch_bounds__(128) void scan_kernel(
    const float* __restrict__ S0,
    float* __restrict__ out,
    float* __restrict__ Sf)
{
    const int rg  = blockIdx.x;
    const int b   = blockIdx.y;
    const int tid = threadIdx.x;
    const int rl  = tid >> 3;
    const int cg  = tid & 7;
    const int i   = rg * 16 + rl;
    const int j0  = cg * 8;

    float S[8];
    {
        const float* p = S0 + b * 4096 + i * 64 + j0;
        #pragma unroll
        for (int c = 0; c < 8; c++) S[c] = p[c];
    }

    const float* kp  = g_k  + b * 64 + j0;
    const float* qp  = g_q  + b * 64 + j0;
    const float* ep  = g_e  + b * 64 + i;
    const float* wvp = g_wv + b * 64 + i;
    float*       op  = out  + b * 64 + i;

    float4 k0 = *(const float4*)(kp);
    float4 k1 = *(const float4*)(kp + 4);
    float4 q0 = *(const float4*)(qp);
    float4 q1 = *(const float4*)(qp + 4);
    float ei  = *ep;
    float wvi = *wvp;

    for (int t = 0; t < T_DIM; t++) {
        // software prefetch t+1 (arrays padded, so t=T read is safe)
        const int off = (t + 1) * BN_;
        float4 nk0 = *(const float4*)(kp + off);
        float4 nk1 = *(const float4*)(kp + off + 4);
        float4 nq0 = *(const float4*)(qp + off);
        float4 nq1 = *(const float4*)(qp + off + 4);
        float  nei  = ep[off];
        float  nwvi = wvp[off];

        const float kk[8] = {k0.x, k0.y, k0.z, k0.w, k1.x, k1.y, k1.z, k1.w};
        const float qq[8] = {q0.x, q0.y, q0.z, q0.w, q1.x, q1.y, q1.z, q1.w};

        float dot = 0.f;
        #pragma unroll
        for (int c = 0; c < 8; c++) {
            S[c] = fmaf(kk[c], fmaf(-ei, S[c], wvi), S[c]);
            dot  = fmaf(S[c], qq[c], dot);
        }
        dot += __shfl_xor_sync(0xffffffffu, dot, 1);
        dot += __shfl_xor_sync(0xffffffffu, dot, 2);
        dot += __shfl_xor_sync(0xffffffffu, dot, 4);

        const float o = tanhf(dot);
        if (cg == 0) op[(size_t)t * BN_] = o;

        k0 = nk0; k1 = nk1; q0 = nq0; q1 = nq1; ei = nei; wvi = nwvi;
    }

    float* sp = Sf + b * 4096 + i * 64 + j0;
    #pragma unroll
    for (int c = 0; c < 8; c++) sp[c] = S[c];
}

// ---------------------------------------------------------------------------
extern "C" void kernel_launch(void* const* d_in, const int* in_sizes, int n_in,
                              void* d_out, int out_size)
{
    const float* x  = (const float*)d_in[0];
    const float* S0 = (const float*)d_in[1];
    const float* Wk = (const float*)d_in[2];
    const float* Wv = (const float*)d_in[3];
    const float* Wq = (const float*)d_in[4];
    const float* We = (const float*)d_in[5];
    const float* Ww = (const float*)d_in[6];

    float* out = (float*)d_out;            // [T,B,N] output
    float* Sf  = out + TBN_;               // [B,N,N] final state

    gates_kernel<<<dim3(T_DIM, 4), 256>>>(x, Wk, Wv, Wq, We, Ww);
    scan_kernel<<<dim3(4, B_DIM), 128>>>(S0, out, Sf);
}

// round 3
// speedup vs baseline: 1.7831x; 1.7831x over previous
#include <cuda_runtime.h>
#include <math.h>

#define T_DIM 1024
#define B_DIM 64
#define D_DIM 512
#define N_DIM 64
#define BN_ (B_DIM * N_DIM)          /* 4096 */
#define TBN_ (T_DIM * BN_)           /* 4,194,304 */

// Scratch, padded by TWO timesteps for the scan's 2-deep prefetch
__device__ float g_k [TBN_ + 2 * BN_];
__device__ float g_q [TBN_ + 2 * BN_];
__device__ float g_e [TBN_ + 2 * BN_];
__device__ float g_wv[TBN_ + 2 * BN_];

__device__ __forceinline__ float sigmoidf_(float x) {
    return 1.0f / (1.0f + __expf(-x));
}

// ---- packed fp32x2 helpers (sm_100 f32x2 pipe; 2 FMAs per instruction) ----
__device__ __forceinline__ unsigned long long pack2(float x, float y) {
    unsigned long long r;
    asm("mov.b64 %0, {%1, %2};" : "=l"(r) : "f"(x), "f"(y));
    return r;
}
__device__ __forceinline__ void unpack2(unsigned long long v, float& x, float& y) {
    asm("mov.b64 {%0, %1}, %2;" : "=f"(x), "=f"(y) : "l"(v));
}
__device__ __forceinline__ void ffma2(unsigned long long& d,
                                      unsigned long long a,
                                      unsigned long long b) {
    asm("fma.rn.f32x2 %0, %1, %2, %0;" : "+l"(d) : "l"(a), "l"(b));
}

// ---------------------------------------------------------------------------
// Gates: one batched GEMM over all TB=65536 rows.
// grid (512 row-tiles, 4 gates), block 256. Tile 128 rows x 64 cols, BK=32.
// Microtile 8x4 per thread, accumulated in f32x2 pairs.
//  g=0: k = softmax(x Wk^T)   g=1: q = softmax(x Wq^T)
//  g=2: e = sigmoid(x We^T)   g=3: wv = sigmoid(x Ww^T) * (x Wv^T)
// smem layout: As[128][33] row-major (pad 33 -> conflict-free STS, LDS.32
// broadcast reads), Ws/Ws2[32][68] k-major (pad 68 -> float4 aligned, B pairs
// read directly as double2 for f32x2).
// ---------------------------------------------------------------------------
__global__ __launch_bounds__(256, 2) void gates_kernel(
    const float* __restrict__ x,
    const float* __restrict__ Wk, const float* __restrict__ Wv,
    const float* __restrict__ Wq, const float* __restrict__ We,
    const float* __restrict__ Ww)
{
    __shared__ float sm[4224 + 2176 + 2176];   // 34.3 KB
    float* As  = sm;           // [row*33 + k]
    float* Ws  = sm + 4224;    // [k*68 + n]
    float* Ws2 = sm + 6400;    // [k*68 + n]

    const int g   = blockIdx.y;
    const int r0  = blockIdx.x * 128;
    const int tid = threadIdx.x;
    const int tr  = tid >> 4;          // 0..15 -> rows tr*8..tr*8+7
    const int tc  = tid & 15;          // 0..15 -> cols tc*4..tc*4+3

    const float* W1 = (g == 0) ? Wk : (g == 1) ? Wq : (g == 2) ? We : Ww;

    unsigned long long acc [8][2];
    unsigned long long acc2[8][2];
    #pragma unroll
    for (int i = 0; i < 8; i++) {
        acc[i][0] = 0ull; acc[i][1] = 0ull;
        acc2[i][0] = 0ull; acc2[i][1] = 0ull;
    }

    const float* A = x + (size_t)r0 * D_DIM;

    for (int kt = 0; kt < D_DIM / 32; kt++) {
        const int d0 = kt * 32;
        __syncthreads();
        // load A tile 128x32 (coalesced float4; conflict-free STS via pad 33)
        #pragma unroll
        for (int l = 0; l < 4; l++) {
            const int idx = tid + l * 256;
            const int row = idx >> 3;
            const int c4  = idx & 7;
            float4 v = *(const float4*)(A + (size_t)row * D_DIM + d0 + c4 * 4);
            As[row * 33 + c4 * 4 + 0] = v.x;
            As[row * 33 + c4 * 4 + 1] = v.y;
            As[row * 33 + c4 * 4 + 2] = v.z;
            As[row * 33 + c4 * 4 + 3] = v.w;
        }
        // load W tile(s) 64x32, stored k-major
        #pragma unroll
        for (int l = 0; l < 2; l++) {
            const int idx = tid + l * 256;
            const int row = idx >> 3;          // n
            const int c4  = idx & 7;
            float4 v = *(const float4*)(W1 + row * D_DIM + d0 + c4 * 4);
            Ws[(c4 * 4 + 0) * 68 + row] = v.x;
            Ws[(c4 * 4 + 1) * 68 + row] = v.y;
            Ws[(c4 * 4 + 2) * 68 + row] = v.z;
            Ws[(c4 * 4 + 3) * 68 + row] = v.w;
            if (g == 3) {
                float4 u = *(const float4*)(Wv + row * D_DIM + d0 + c4 * 4);
                Ws2[(c4 * 4 + 0) * 68 + row] = u.x;
                Ws2[(c4 * 4 + 1) * 68 + row] = u.y;
                Ws2[(c4 * 4 + 2) * 68 + row] = u.z;
                Ws2[(c4 * 4 + 3) * 68 + row] = u.w;
            }
        }
        __syncthreads();

        const float* arow = As + tr * 8 * 33;
        #pragma unroll 8
        for (int kk = 0; kk < 32; kk++) {
            double2 bb = *(const double2*)(Ws + kk * 68 + tc * 4);
            unsigned long long b0 = __double_as_longlong(bb.x);
            unsigned long long b1 = __double_as_longlong(bb.y);
            if (g == 3) {
                double2 cc = *(const double2*)(Ws2 + kk * 68 + tc * 4);
                unsigned long long c0 = __double_as_longlong(cc.x);
                unsigned long long c1 = __double_as_longlong(cc.y);
                #pragma unroll
                for (int i = 0; i < 8; i++) {
                    float a = arow[i * 33 + kk];
                    unsigned long long ad = pack2(a, a);
                    ffma2(acc [i][0], ad, b0);
                    ffma2(acc [i][1], ad, b1);
                    ffma2(acc2[i][0], ad, c0);
                    ffma2(acc2[i][1], ad, c1);
                }
            } else {
                #pragma unroll
                for (int i = 0; i < 8; i++) {
                    float a = arow[i * 33 + kk];
                    unsigned long long ad = pack2(a, a);
                    ffma2(acc[i][0], ad, b0);
                    ffma2(acc[i][1], ad, b1);
                }
            }
        }
    }

    if (g == 2) {
        #pragma unroll
        for (int i = 0; i < 8; i++) {
            float v0, v1, v2, v3;
            unpack2(acc[i][0], v0, v1);
            unpack2(acc[i][1], v2, v3);
            float4 o = make_float4(sigmoidf_(v0), sigmoidf_(v1),
                                   sigmoidf_(v2), sigmoidf_(v3));
            *(float4*)(g_e + (size_t)(r0 + tr * 8 + i) * 64 + tc * 4) = o;
        }
    } else if (g == 3) {
        #pragma unroll
        for (int i = 0; i < 8; i++) {
            float w0, w1, w2, w3, v0, v1, v2, v3;
            unpack2(acc [i][0], w0, w1);
            unpack2(acc [i][1], w2, w3);
            unpack2(acc2[i][0], v0, v1);
            unpack2(acc2[i][1], v2, v3);
            float4 o = make_float4(sigmoidf_(w0) * v0, sigmoidf_(w1) * v1,
                                   sigmoidf_(w2) * v2, sigmoidf_(w3) * v3);
            *(float4*)(g_wv + (size_t)(r0 + tr * 8 + i) * 64 + tc * 4) = o;
        }
    } else {
        // stage logits to smem, then row softmax (2 threads per row)
        float* Ls = sm;                           // 8192 floats needed, have 8576
        __syncthreads();
        #pragma unroll
        for (int i = 0; i < 8; i++) {
            float v0, v1, v2, v3;
            unpack2(acc[i][0], v0, v1);
            unpack2(acc[i][1], v2, v3);
            *(float4*)(Ls + (tr * 8 + i) * 64 + tc * 4) = make_float4(v0, v1, v2, v3);
        }
        __syncthreads();

        const int row  = tid >> 1;                // 0..127
        const int part = tid & 1;                 // halves of the row
        float v[32];
        const float* rp = Ls + row * 64 + part * 32;
        #pragma unroll
        for (int c = 0; c < 32; c += 4) {
            float4 t4 = *(const float4*)(rp + c);
            v[c] = t4.x; v[c+1] = t4.y; v[c+2] = t4.z; v[c+3] = t4.w;
        }
        float m = v[0];
        #pragma unroll
        for (int c = 1; c < 32; c++) m = fmaxf(m, v[c]);
        m = fmaxf(m, __shfl_xor_sync(0xffffffffu, m, 1));
        float s = 0.f;
        #pragma unroll
        for (int c = 0; c < 32; c++) { v[c] = __expf(v[c] - m); s += v[c]; }
        s += __shfl_xor_sync(0xffffffffu, s, 1);
        const float inv = 1.0f / s;

        float* dst = ((g == 0) ? g_k : g_q) + (size_t)(r0 + row) * 64 + part * 32;
        #pragma unroll
        for (int c = 0; c < 32; c += 4)
            *(float4*)(dst + c) = make_float4(v[c] * inv, v[c+1] * inv,
                                              v[c+2] * inv, v[c+3] * inv);
    }
}

// ---------------------------------------------------------------------------
// Scan: warp per (b, i) row. 4096 warps total. Lane owns cols {2*lane, 2*lane+1}.
// 2-step software prefetch covers L2/DRAM latency.
// ---------------------------------------------------------------------------
__global__ __launch_bounds__(128) void scan_kernel(
    const float* __restrict__ S0,
    float* __restrict__ out,
    float* __restrict__ Sf)
{
    const int b    = blockIdx.y;
    const int i    = blockIdx.x * 4 + (threadIdx.x >> 5);
    const int lane = threadIdx.x & 31;
    const int j0   = lane * 2;

    float2 S = *(const float2*)(S0 + (size_t)b * 4096 + i * 64 + j0);

    const float* kp  = g_k  + b * 64 + j0;
    const float* qp  = g_q  + b * 64 + j0;
    const float* ep  = g_e  + b * 64 + i;
    const float* wvp = g_wv + b * 64 + i;
    float*       op  = out  + b * 64 + i;

    // pipeline: cur = t, nxt = t+1 (arrays padded +2 steps)
    float2 k_c = *(const float2*)(kp);
    float2 q_c = *(const float2*)(qp);
    float  e_c = *ep, wv_c = *wvp;
    float2 k_n = *(const float2*)(kp + BN_);
    float2 q_n = *(const float2*)(qp + BN_);
    float  e_n = ep[BN_], wv_n = wvp[BN_];

    for (int t = 0; t < T_DIM; t++) {
        const int off = (t + 2) * BN_;
        float2 k_f = *(const float2*)(kp + off);
        float2 q_f = *(const float2*)(qp + off);
        float  e_f = ep[off];
        float  wv_f = wvp[off];

        S.x = fmaf(k_c.x, fmaf(-e_c, S.x, wv_c), S.x);
        S.y = fmaf(k_c.y, fmaf(-e_c, S.y, wv_c), S.y);

        float dot = fmaf(S.x, q_c.x, S.y * q_c.y);
        dot += __shfl_xor_sync(0xffffffffu, dot, 16);
        dot += __shfl_xor_sync(0xffffffffu, dot, 8);
        dot += __shfl_xor_sync(0xffffffffu, dot, 4);
        dot += __shfl_xor_sync(0xffffffffu, dot, 2);
        dot += __shfl_xor_sync(0xffffffffu, dot, 1);

        const float o = tanhf(dot);
        if (lane == 0) op[(size_t)t * BN_] = o;

        k_c = k_n; q_c = q_n; e_c = e_n; wv_c = wv_n;
        k_n = k_f; q_n = q_f; e_n = e_f; wv_n = wv_f;
    }

    *(float2*)(Sf + (size_t)b * 4096 + i * 64 + j0) = S;
}

// ---------------------------------------------------------------------------
extern "C" void kernel_launch(void* const* d_in, const int* in_sizes, int n_in,
                              void* d_out, int out_size)
{
    const float* x  = (const float*)d_in[0];
    const float* S0 = (const float*)d_in[1];
    const float* Wk = (const float*)d_in[2];
    const float* Wv = (const float*)d_in[3];
    const float* Wq = (const float*)d_in[4];
    const float* We = (const float*)d_in[5];
    const float* Ww = (const float*)d_in[6];

    float* out = (float*)d_out;            // [T,B,N]
    float* Sf  = out + TBN_;               // [B,N,N]

    gates_kernel<<<dim3(512, 4), 256>>>(x, Wk, Wv, Wq, We, Ww);
    scan_kernel<<<dim3(16, B_DIM), 128>>>(S0, out, Sf);
}

// round 4
// speedup vs baseline: 1.9542x; 1.0960x over previous
#include <cuda_runtime.h>
#include <math.h>

#define T_DIM 1024
#define B_DIM 64
#define D_DIM 512
#define N_DIM 64
#define BN_ (B_DIM * N_DIM)          /* 4096 */
#define TBN_ (T_DIM * BN_)           /* 4,194,304 */

// Scratch, padded by FOUR timesteps for the scan's depth-3 circular prefetch
__device__ float g_k [TBN_ + 4 * BN_];
__device__ float g_q [TBN_ + 4 * BN_];
__device__ float g_e [TBN_ + 4 * BN_];
__device__ float g_wv[TBN_ + 4 * BN_];

__device__ __forceinline__ float sigmoidf_(float x) {
    return 1.0f / (1.0f + __expf(-x));
}

// ---- packed fp32x2 helpers ----
__device__ __forceinline__ unsigned long long pack2(float x, float y) {
    unsigned long long r;
    asm("mov.b64 %0, {%1, %2};" : "=l"(r) : "f"(x), "f"(y));
    return r;
}
__device__ __forceinline__ void unpack2(unsigned long long v, float& x, float& y) {
    asm("mov.b64 {%0, %1}, %2;" : "=f"(x), "=f"(y) : "l"(v));
}
__device__ __forceinline__ void ffma2(unsigned long long& d,
                                      unsigned long long a,
                                      unsigned long long b) {
    asm("fma.rn.f32x2 %0, %1, %2, %0;" : "+l"(d) : "l"(a), "l"(b));
}

// ---------------------------------------------------------------------------
// Gates GEMM, register-staged double buffer.
// grid (512 row-tiles, 4 gates), block 256. Tile 128 rows x 64 cols, BK=32.
// ---------------------------------------------------------------------------
__global__ __launch_bounds__(256, 2) void gates_kernel(
    const float* __restrict__ x,
    const float* __restrict__ Wk, const float* __restrict__ Wv,
    const float* __restrict__ Wq, const float* __restrict__ We,
    const float* __restrict__ Ww)
{
    __shared__ float sm[4224 + 2176 + 2176];
    float* As  = sm;           // [row*33 + k]
    float* Ws  = sm + 4224;    // [k*68 + n]
    float* Ws2 = sm + 6400;

    const int g   = blockIdx.y;
    const int r0  = blockIdx.x * 128;
    const int tid = threadIdx.x;
    const int tr  = tid >> 4;
    const int tc  = tid & 15;

    const float* W1 = (g == 0) ? Wk : (g == 1) ? Wq : (g == 2) ? We : Ww;

    unsigned long long acc [8][2];
    unsigned long long acc2[8][2];
    #pragma unroll
    for (int i = 0; i < 8; i++) {
        acc[i][0] = 0ull; acc[i][1] = 0ull;
        acc2[i][0] = 0ull; acc2[i][1] = 0ull;
    }

    const float* A = x + (size_t)r0 * D_DIM;

    // staging registers
    float4 a_st[4];
    float4 w_st[2];
    float4 w2_st[2];

    const int a_row = tid >> 3;          // for A loads: idx = tid + l*256
    const int a_c4  = tid & 7;

    // prologue: fetch chunk 0
    {
        const int d0 = 0;
        #pragma unroll
        for (int l = 0; l < 4; l++) {
            const int row = (tid + l * 256) >> 3;
            a_st[l] = *(const float4*)(A + (size_t)row * D_DIM + d0 + a_c4 * 4);
        }
        #pragma unroll
        for (int l = 0; l < 2; l++) {
            const int row = (tid + l * 256) >> 3;
            w_st[l] = *(const float4*)(W1 + row * D_DIM + d0 + a_c4 * 4);
            if (g == 3)
                w2_st[l] = *(const float4*)(Wv + row * D_DIM + d0 + a_c4 * 4);
        }
    }

    for (int kt = 0; kt < 16; kt++) {
        __syncthreads();   // previous compute done reading smem
        // STS staged chunk
        #pragma unroll
        for (int l = 0; l < 4; l++) {
            const int row = (tid + l * 256) >> 3;
            As[row * 33 + a_c4 * 4 + 0] = a_st[l].x;
            As[row * 33 + a_c4 * 4 + 1] = a_st[l].y;
            As[row * 33 + a_c4 * 4 + 2] = a_st[l].z;
            As[row * 33 + a_c4 * 4 + 3] = a_st[l].w;
        }
        #pragma unroll
        for (int l = 0; l < 2; l++) {
            const int row = (tid + l * 256) >> 3;
            Ws[(a_c4 * 4 + 0) * 68 + row] = w_st[l].x;
            Ws[(a_c4 * 4 + 1) * 68 + row] = w_st[l].y;
            Ws[(a_c4 * 4 + 2) * 68 + row] = w_st[l].z;
            Ws[(a_c4 * 4 + 3) * 68 + row] = w_st[l].w;
            if (g == 3) {
                Ws2[(a_c4 * 4 + 0) * 68 + row] = w2_st[l].x;
                Ws2[(a_c4 * 4 + 1) * 68 + row] = w2_st[l].y;
                Ws2[(a_c4 * 4 + 2) * 68 + row] = w2_st[l].z;
                Ws2[(a_c4 * 4 + 3) * 68 + row] = w2_st[l].w;
            }
        }
        __syncthreads();

        // issue next chunk's LDGs (overlap with compute)
        if (kt < 15) {
            const int d0 = (kt + 1) * 32;
            #pragma unroll
            for (int l = 0; l < 4; l++) {
                const int row = (tid + l * 256) >> 3;
                a_st[l] = *(const float4*)(A + (size_t)row * D_DIM + d0 + a_c4 * 4);
            }
            #pragma unroll
            for (int l = 0; l < 2; l++) {
                const int row = (tid + l * 256) >> 3;
                w_st[l] = *(const float4*)(W1 + row * D_DIM + d0 + a_c4 * 4);
                if (g == 3)
                    w2_st[l] = *(const float4*)(Wv + row * D_DIM + d0 + a_c4 * 4);
            }
        }

        const float* arow = As + tr * 8 * 33;
        #pragma unroll 8
        for (int kk = 0; kk < 32; kk++) {
            double2 bb = *(const double2*)(Ws + kk * 68 + tc * 4);
            unsigned long long b0 = __double_as_longlong(bb.x);
            unsigned long long b1 = __double_as_longlong(bb.y);
            if (g == 3) {
                double2 cc = *(const double2*)(Ws2 + kk * 68 + tc * 4);
                unsigned long long c0 = __double_as_longlong(cc.x);
                unsigned long long c1 = __double_as_longlong(cc.y);
                #pragma unroll
                for (int i = 0; i < 8; i++) {
                    float a = arow[i * 33 + kk];
                    unsigned long long ad = pack2(a, a);
                    ffma2(acc [i][0], ad, b0);
                    ffma2(acc [i][1], ad, b1);
                    ffma2(acc2[i][0], ad, c0);
                    ffma2(acc2[i][1], ad, c1);
                }
            } else {
                #pragma unroll
                for (int i = 0; i < 8; i++) {
                    float a = arow[i * 33 + kk];
                    unsigned long long ad = pack2(a, a);
                    ffma2(acc[i][0], ad, b0);
                    ffma2(acc[i][1], ad, b1);
                }
            }
        }
    }

    if (g == 2) {
        #pragma unroll
        for (int i = 0; i < 8; i++) {
            float v0, v1, v2, v3;
            unpack2(acc[i][0], v0, v1);
            unpack2(acc[i][1], v2, v3);
            float4 o = make_float4(sigmoidf_(v0), sigmoidf_(v1),
                                   sigmoidf_(v2), sigmoidf_(v3));
            *(float4*)(g_e + (size_t)(r0 + tr * 8 + i) * 64 + tc * 4) = o;
        }
    } else if (g == 3) {
        #pragma unroll
        for (int i = 0; i < 8; i++) {
            float w0, w1, w2, w3, v0, v1, v2, v3;
            unpack2(acc [i][0], w0, w1);
            unpack2(acc [i][1], w2, w3);
            unpack2(acc2[i][0], v0, v1);
            unpack2(acc2[i][1], v2, v3);
            float4 o = make_float4(sigmoidf_(w0) * v0, sigmoidf_(w1) * v1,
                                   sigmoidf_(w2) * v2, sigmoidf_(w3) * v3);
            *(float4*)(g_wv + (size_t)(r0 + tr * 8 + i) * 64 + tc * 4) = o;
        }
    } else {
        float* Ls = sm;
        __syncthreads();
        #pragma unroll
        for (int i = 0; i < 8; i++) {
            float v0, v1, v2, v3;
            unpack2(acc[i][0], v0, v1);
            unpack2(acc[i][1], v2, v3);
            *(float4*)(Ls + (tr * 8 + i) * 64 + tc * 4) = make_float4(v0, v1, v2, v3);
        }
        __syncthreads();

        const int row  = tid >> 1;
        const int part = tid & 1;
        float v[32];
        const float* rp = Ls + row * 64 + part * 32;
        #pragma unroll
        for (int c = 0; c < 32; c += 4) {
            float4 t4 = *(const float4*)(rp + c);
            v[c] = t4.x; v[c+1] = t4.y; v[c+2] = t4.z; v[c+3] = t4.w;
        }
        float m = v[0];
        #pragma unroll
        for (int c = 1; c < 32; c++) m = fmaxf(m, v[c]);
        m = fmaxf(m, __shfl_xor_sync(0xffffffffu, m, 1));
        float s = 0.f;
        #pragma unroll
        for (int c = 0; c < 32; c++) { v[c] = __expf(v[c] - m); s += v[c]; }
        s += __shfl_xor_sync(0xffffffffu, s, 1);
        const float inv = 1.0f / s;

        float* dst = ((g == 0) ? g_k : g_q) + (size_t)(r0 + row) * 64 + part * 32;
        #pragma unroll
        for (int c = 0; c < 32; c += 4)
            *(float4*)(dst + c) = make_float4(v[c] * inv, v[c+1] * inv,
                                              v[c+2] * inv, v[c+3] * inv);
    }
}

// ---------------------------------------------------------------------------
// Scan: 2 rows per warp (16 lanes each, 4 cols per lane).
// 4-shfl butterfly reduces both rows at once; fast exp-based tanh;
// depth-3 circular prefetch, t-loop unrolled x4 (no rotation movs).
// ---------------------------------------------------------------------------
__global__ __launch_bounds__(128) void scan_kernel(
    const float* __restrict__ S0,
    float* __restrict__ out,
    float* __restrict__ Sf)
{
    const int b    = blockIdx.y;
    const int warp = threadIdx.x >> 5;
    const int lane = threadIdx.x & 31;
    const int half = lane >> 4;                 // row within warp
    const int sub  = lane & 15;                 // lane within row
    const int i    = blockIdx.x * 8 + warp * 2 + half;
    const int j0   = sub * 4;

    float4 S = *(const float4*)(S0 + (size_t)b * 4096 + i * 64 + j0);

    const float* kp  = g_k  + b * 64 + j0;
    const float* qp  = g_q  + b * 64 + j0;
    const float* ep  = g_e  + b * 64 + i;
    const float* wvp = g_wv + b * 64 + i;
    float*       op  = out  + b * 64 + i;

    float4 kb[4], qb[4];
    float  eb[4], wb[4];

    #pragma unroll
    for (int s = 0; s < 3; s++) {               // prologue: t = 0,1,2
        kb[s] = *(const float4*)(kp + s * BN_);
        qb[s] = *(const float4*)(qp + s * BN_);
        eb[s] = ep[s * BN_];
        wb[s] = wvp[s * BN_];
    }

    for (int t = 0; t < T_DIM; t += 4) {
        #pragma unroll
        for (int tt = 0; tt < 4; tt++) {
            const int cur = tt;                  // (t+tt)&3 == tt since t%4==0
            const int nxt = (tt + 3) & 3;
            const int off = (t + tt + 3) * BN_;  // padded +4, safe at end
            kb[nxt] = *(const float4*)(kp + off);
            qb[nxt] = *(const float4*)(qp + off);
            eb[nxt] = ep[off];
            wb[nxt] = wvp[off];

            const float e = eb[cur], wv = wb[cur];
            const float4 k = kb[cur], q = qb[cur];

            S.x = fmaf(k.x, fmaf(-e, S.x, wv), S.x);
            S.y = fmaf(k.y, fmaf(-e, S.y, wv), S.y);
            S.z = fmaf(k.z, fmaf(-e, S.z, wv), S.z);
            S.w = fmaf(k.w, fmaf(-e, S.w, wv), S.w);

            float dot = fmaf(S.x, q.x, S.y * q.y);
            dot = fmaf(S.z, q.z, dot);
            dot = fmaf(S.w, q.w, dot);
            dot += __shfl_xor_sync(0xffffffffu, dot, 8);
            dot += __shfl_xor_sync(0xffffffffu, dot, 4);
            dot += __shfl_xor_sync(0xffffffffu, dot, 2);
            dot += __shfl_xor_sync(0xffffffffu, dot, 1);

            // fast tanh: clamp + expf
            float xc = fminf(fmaxf(dot, -9.0f), 9.0f);
            float ex = __expf(2.0f * xc);
            float o  = __fdividef(ex - 1.0f, ex + 1.0f);
            if (sub == 0) op[(size_t)(t + tt) * BN_] = o;
        }
    }

    *(float4*)(Sf + (size_t)b * 4096 + i * 64 + j0) = S;
}

// ---------------------------------------------------------------------------
extern "C" void kernel_launch(void* const* d_in, const int* in_sizes, int n_in,
                              void* d_out, int out_size)
{
    const float* x  = (const float*)d_in[0];
    const float* S0 = (const float*)d_in[1];
    const float* Wk = (const float*)d_in[2];
    const float* Wv = (const float*)d_in[3];
    const float* Wq = (const float*)d_in[4];
    const float* We = (const float*)d_in[5];
    const float* Ww = (const float*)d_in[6];

    float* out = (float*)d_out;            // [T,B,N]
    float* Sf  = out + TBN_;               // [B,N,N]

    gates_kernel<<<dim3(512, 4), 256>>>(x, Wk, Wv, Wq, We, Ww);
    scan_kernel<<<dim3(8, B_DIM), 128>>>(S0, out, Sf);
}

// round 5
// speedup vs baseline: 3.4116x; 1.7458x over previous
#include <cuda_runtime.h>
#include <cuda_bf16.h>
#include <math.h>

typedef unsigned int u32;

#define T_DIM 1024
#define B_DIM 64
#define D_DIM 512
#define N_DIM 64
#define BN_ (B_DIM * N_DIM)          /* 4096 */
#define TBN_ (T_DIM * BN_)           /* 4,194,304 */

// Scratch, padded by FOUR timesteps for the scan's depth-3 circular prefetch
__device__ float g_k [TBN_ + 4 * BN_];
__device__ float g_q [TBN_ + 4 * BN_];
__device__ float g_e [TBN_ + 4 * BN_];
__device__ float g_wv[TBN_ + 4 * BN_];

// Concatenated weights, bf16 hi/lo split. Row order:
// [0:64)=Wk  [64:128)=Wq  [128:192)=We  [192:256)=Ww  [256:320)=Wv
__device__ __align__(16) __nv_bfloat16 g_Whi[320 * 512];
__device__ __align__(16) __nv_bfloat16 g_Wlo[320 * 512];

__device__ __forceinline__ float sigmoidf_(float x) {
    return 1.0f / (1.0f + __expf(-x));
}
__device__ __forceinline__ u32 pk(__nv_bfloat16 a, __nv_bfloat16 b) {
    __nv_bfloat162 t = __halves2bfloat162(a, b);   // .x = a = low 16 bits
    return *(u32*)&t;
}
__device__ __forceinline__ void cpasync16(void* s, const void* g) {
    u32 sa = (u32)__cvta_generic_to_shared(s);
    asm volatile("cp.async.cg.shared.global [%0], [%1], 16;\n" :: "r"(sa), "l"(g));
}
__device__ __forceinline__ void mma16816(float* d, const u32* a, const u32* b) {
    asm volatile(
        "mma.sync.aligned.m16n8k16.row.col.f32.bf16.bf16.f32 "
        "{%0,%1,%2,%3},{%4,%5,%6,%7},{%8,%9},{%0,%1,%2,%3};"
        : "+f"(d[0]), "+f"(d[1]), "+f"(d[2]), "+f"(d[3])
        : "r"(a[0]), "r"(a[1]), "r"(a[2]), "r"(a[3]), "r"(b[0]), "r"(b[1]));
}

// ---------------------------------------------------------------------------
// W conversion prepass: 5 x [64,512] f32 -> [320,512] bf16 hi/lo.
// ---------------------------------------------------------------------------
__global__ void convw_kernel(const float* __restrict__ Wk, const float* __restrict__ Wq,
                             const float* __restrict__ We, const float* __restrict__ Ww,
                             const float* __restrict__ Wv)
{
    const int row = blockIdx.x;          // 0..319
    const int tid = threadIdx.x;         // 0..127
    const float* src = (row < 64) ? Wk : (row < 128) ? Wq :
                       (row < 192) ? We : (row < 256) ? Ww : Wv;
    const int r = row & 63;
    float4 v = *(const float4*)(src + r * 512 + tid * 4);
    float vv[4] = {v.x, v.y, v.z, v.w};
    __nv_bfloat16 h[4], l[4];
    #pragma unroll
    for (int j = 0; j < 4; j++) {
        h[j] = __float2bfloat16(vv[j]);
        l[j] = __float2bfloat16(vv[j] - __bfloat162float(h[j]));
    }
    *(uint2*)(g_Whi + row * 512 + tid * 4) = make_uint2(pk(h[0], h[1]), pk(h[2], h[3]));
    *(uint2*)(g_Wlo + row * 512 + tid * 4) = make_uint2(pk(l[0], l[1]), pk(l[2], l[3]));
}

// ---------------------------------------------------------------------------
// Gates GEMM on tensor cores (bf16 3-split). grid 1024, block 512.
// CTA: 64 rows x 320 cols, K=512 in 8 chunks of 64.
// smem: A hi/lo [64][72] bf16 (single buf, reg-staged+converted),
//       B hi/lo [320][72] bf16 x2 buffers (cp.async double buffer).
// Warp (16): wm = warp>>3 (2), wn = warp&7 (8); warp tile 32 x 40.
// ---------------------------------------------------------------------------
#define A_ELEMS (64 * 72)                /* 4608 per hi/lo */
#define B_ELEMS (320 * 72)               /* 23040 per hi/lo */
#define BBUF_ELEMS (2 * B_ELEMS)         /* hi+lo per buffer */
#define SMEM_BYTES ((2 * A_ELEMS + 2 * BBUF_ELEMS) * 2)   /* 202752 */

__global__ __launch_bounds__(512, 1) void gates_kernel(const float* __restrict__ x)
{
    extern __shared__ char smem_raw[];
    __nv_bfloat16* Ahi = (__nv_bfloat16*)smem_raw;
    __nv_bfloat16* Alo = Ahi + A_ELEMS;
    __nv_bfloat16* Bb  = Alo + A_ELEMS;   // buffer b: hi at Bb + b*BBUF_ELEMS, lo at +B_ELEMS

    const int tid  = threadIdx.x;
    const int lane = tid & 31;
    const int warp = tid >> 5;
    const int wm = warp >> 3;             // 0..1
    const int wn = warp & 7;              // 0..7
    const int gid = lane >> 2;            // 0..7
    const int t4  = lane & 3;             // 0..3
    const int r0  = blockIdx.x * 64;

    float acc[2][5][4];
    #pragma unroll
    for (int mt = 0; mt < 2; mt++)
        #pragma unroll
        for (int nt = 0; nt < 5; nt++)
            #pragma unroll
            for (int c = 0; c < 4; c++) acc[mt][nt][c] = 0.f;

    // A staging addressing: row = tid>>3 (0..63), c8 = (tid&7)*8
    const int a_row = tid >> 3;
    const int a_c8  = (tid & 7) * 8;
    const float* a_src = x + (size_t)(r0 + a_row) * 512 + a_c8;

    // --- prologue: issue B chunk 0 (cp.async group 0), A chunk 0 (regs) ---
    #pragma unroll
    for (int it = 0; it < 5; it++) {
        const int idx = tid + it * 512;        // < 2560 always
        const int row = idx >> 3, seg = idx & 7;
        cpasync16(Bb + row * 72 + seg * 8,            g_Whi + row * 512 + seg * 8);
        cpasync16(Bb + B_ELEMS + row * 72 + seg * 8,  g_Wlo + row * 512 + seg * 8);
    }
    asm volatile("cp.async.commit_group;");
    float4 xa0 = *(const float4*)(a_src);
    float4 xa1 = *(const float4*)(a_src + 4);

    for (int ct = 0; ct < 8; ct++) {
        __syncthreads();                       // A buf + prev B buf free
        // convert + STS A(ct)
        {
            float vv[8] = {xa0.x, xa0.y, xa0.z, xa0.w, xa1.x, xa1.y, xa1.z, xa1.w};
            __nv_bfloat16 h[8], l[8];
            #pragma unroll
            for (int j = 0; j < 8; j++) {
                h[j] = __float2bfloat16(vv[j]);
                l[j] = __float2bfloat16(vv[j] - __bfloat162float(h[j]));
            }
            *(uint4*)(Ahi + a_row * 72 + a_c8) =
                make_uint4(pk(h[0],h[1]), pk(h[2],h[3]), pk(h[4],h[5]), pk(h[6],h[7]));
            *(uint4*)(Alo + a_row * 72 + a_c8) =
                make_uint4(pk(l[0],l[1]), pk(l[2],l[3]), pk(l[4],l[5]), pk(l[6],l[7]));
        }
        // issue next chunk loads
        if (ct < 7) {
            const int k0n = (ct + 1) * 64;
            __nv_bfloat16* Bn = Bb + ((ct + 1) & 1) * BBUF_ELEMS;
            #pragma unroll
            for (int it = 0; it < 5; it++) {
                const int idx = tid + it * 512;
                const int row = idx >> 3, seg = idx & 7;
                cpasync16(Bn + row * 72 + seg * 8,           g_Whi + row * 512 + k0n + seg * 8);
                cpasync16(Bn + B_ELEMS + row * 72 + seg * 8, g_Wlo + row * 512 + k0n + seg * 8);
            }
            asm volatile("cp.async.commit_group;");
            xa0 = *(const float4*)(a_src + k0n);
            xa1 = *(const float4*)(a_src + k0n + 4);
            asm volatile("cp.async.wait_group 1;");
        } else {
            asm volatile("cp.async.wait_group 0;");
        }
        __syncthreads();                       // A(ct) + B(ct) visible to all

        const __nv_bfloat16* Bhi = Bb + (ct & 1) * BBUF_ELEMS;
        const __nv_bfloat16* Blo = Bhi + B_ELEMS;

        #pragma unroll
        for (int ks = 0; ks < 4; ks++) {
            const int kc = ks * 16 + t4 * 2;
            u32 ah[2][4], al[2][4], bh[5][2], bl[5][2];
            #pragma unroll
            for (int mt = 0; mt < 2; mt++) {
                const int r1 = wm * 32 + mt * 16 + gid;
                ah[mt][0] = *(const u32*)(Ahi + r1 * 72 + kc);
                ah[mt][1] = *(const u32*)(Ahi + (r1 + 8) * 72 + kc);
                ah[mt][2] = *(const u32*)(Ahi + r1 * 72 + kc + 8);
                ah[mt][3] = *(const u32*)(Ahi + (r1 + 8) * 72 + kc + 8);
                al[mt][0] = *(const u32*)(Alo + r1 * 72 + kc);
                al[mt][1] = *(const u32*)(Alo + (r1 + 8) * 72 + kc);
                al[mt][2] = *(const u32*)(Alo + r1 * 72 + kc + 8);
                al[mt][3] = *(const u32*)(Alo + (r1 + 8) * 72 + kc + 8);
            }
            #pragma unroll
            for (int nt = 0; nt < 5; nt++) {
                const int n = wn * 40 + nt * 8 + gid;
                bh[nt][0] = *(const u32*)(Bhi + n * 72 + kc);
                bh[nt][1] = *(const u32*)(Bhi + n * 72 + kc + 8);
                bl[nt][0] = *(const u32*)(Blo + n * 72 + kc);
                bl[nt][1] = *(const u32*)(Blo + n * 72 + kc + 8);
            }
            #pragma unroll
            for (int mt = 0; mt < 2; mt++)
                #pragma unroll
                for (int nt = 0; nt < 5; nt++) mma16816(acc[mt][nt], ah[mt], bh[nt]);
            #pragma unroll
            for (int mt = 0; mt < 2; mt++)
                #pragma unroll
                for (int nt = 0; nt < 5; nt++) mma16816(acc[mt][nt], ah[mt], bl[nt]);
            #pragma unroll
            for (int mt = 0; mt < 2; mt++)
                #pragma unroll
                for (int nt = 0; nt < 5; nt++) mma16816(acc[mt][nt], al[mt], bh[nt]);
        }
    }

    // ---- epilogue: stage D[64][320] to smem (stride 328), fuse activations ----
    float* Ls = (float*)smem_raw;
    __syncthreads();
    #pragma unroll
    for (int mt = 0; mt < 2; mt++) {
        const int row1 = wm * 32 + mt * 16 + gid;
        #pragma unroll
        for (int nt = 0; nt < 5; nt++) {
            const int col = wn * 40 + nt * 8 + t4 * 2;
            *(float2*)(Ls + row1 * 328 + col)       = make_float2(acc[mt][nt][0], acc[mt][nt][1]);
            *(float2*)(Ls + (row1 + 8) * 328 + col) = make_float2(acc[mt][nt][2], acc[mt][nt][3]);
        }
    }
    __syncthreads();

    if (tid < 256) {
        // k (cols 0..63) and q (cols 64..127): row softmax, 2 threads per row
        const int gate = tid >> 7;            // 0=k, 1=q
        const int row  = (tid >> 1) & 63;
        const int part = tid & 1;
        const float* rp = Ls + row * 328 + gate * 64 + part * 32;
        float v[32];
        #pragma unroll
        for (int c = 0; c < 32; c += 4) {
            float4 t4v = *(const float4*)(rp + c);
            v[c] = t4v.x; v[c+1] = t4v.y; v[c+2] = t4v.z; v[c+3] = t4v.w;
        }
        float m = v[0];
        #pragma unroll
        for (int c = 1; c < 32; c++) m = fmaxf(m, v[c]);
        m = fmaxf(m, __shfl_xor_sync(0xffffffffu, m, 1));
        float s = 0.f;
        #pragma unroll
        for (int c = 0; c < 32; c++) { v[c] = __expf(v[c] - m); s += v[c]; }
        s += __shfl_xor_sync(0xffffffffu, s, 1);
        const float inv = 1.0f / s;
        float* dst = ((gate == 0) ? g_k : g_q) + (size_t)(r0 + row) * 64 + part * 32;
        #pragma unroll
        for (int c = 0; c < 32; c += 4)
            *(float4*)(dst + c) = make_float4(v[c]*inv, v[c+1]*inv, v[c+2]*inv, v[c+3]*inv);
    } else {
        const int t2 = tid - 256;             // 0..255
        // e = sigmoid(cols 128..191)
        for (int i4 = t2; i4 < 1024; i4 += 256) {
            const int rr = i4 >> 4, c4 = (i4 & 15) * 4;
            float4 a = *(const float4*)(Ls + rr * 328 + 128 + c4);
            *(float4*)(g_e + (size_t)(r0 + rr) * 64 + c4) =
                make_float4(sigmoidf_(a.x), sigmoidf_(a.y), sigmoidf_(a.z), sigmoidf_(a.w));
        }
        // wv = sigmoid(cols 192..255) * cols 256..319
        for (int i4 = t2; i4 < 1024; i4 += 256) {
            const int rr = i4 >> 4, c4 = (i4 & 15) * 4;
            float4 w = *(const float4*)(Ls + rr * 328 + 192 + c4);
            float4 vv = *(const float4*)(Ls + rr * 328 + 256 + c4);
            *(float4*)(g_wv + (size_t)(r0 + rr) * 64 + c4) =
                make_float4(sigmoidf_(w.x)*vv.x, sigmoidf_(w.y)*vv.y,
                            sigmoidf_(w.z)*vv.z, sigmoidf_(w.w)*vv.w);
        }
    }
}

// ---------------------------------------------------------------------------
// Scan: unchanged from R4 (2 rows/warp, depth-3 circular prefetch).
// ---------------------------------------------------------------------------
__global__ __launch_bounds__(128) void scan_kernel(
    const float* __restrict__ S0,
    float* __restrict__ out,
    float* __restrict__ Sf)
{
    const int b    = blockIdx.y;
    const int warp = threadIdx.x >> 5;
    const int lane = threadIdx.x & 31;
    const int half = lane >> 4;
    const int sub  = lane & 15;
    const int i    = blockIdx.x * 8 + warp * 2 + half;
    const int j0   = sub * 4;

    float4 S = *(const float4*)(S0 + (size_t)b * 4096 + i * 64 + j0);

    const float* kp  = g_k  + b * 64 + j0;
    const float* qp  = g_q  + b * 64 + j0;
    const float* ep  = g_e  + b * 64 + i;
    const float* wvp = g_wv + b * 64 + i;
    float*       op  = out  + b * 64 + i;

    float4 kb[4], qb[4];
    float  eb[4], wb[4];
    #pragma unroll
    for (int s = 0; s < 3; s++) {
        kb[s] = *(const float4*)(kp + s * BN_);
        qb[s] = *(const float4*)(qp + s * BN_);
        eb[s] = ep[s * BN_];
        wb[s] = wvp[s * BN_];
    }

    for (int t = 0; t < T_DIM; t += 4) {
        #pragma unroll
        for (int tt = 0; tt < 4; tt++) {
            const int cur = tt;
            const int nxt = (tt + 3) & 3;
            const int off = (t + tt + 3) * BN_;
            kb[nxt] = *(const float4*)(kp + off);
            qb[nxt] = *(const float4*)(qp + off);
            eb[nxt] = ep[off];
            wb[nxt] = wvp[off];

            const float e = eb[cur], wv = wb[cur];
            const float4 k = kb[cur], q = qb[cur];

            S.x = fmaf(k.x, fmaf(-e, S.x, wv), S.x);
            S.y = fmaf(k.y, fmaf(-e, S.y, wv), S.y);
            S.z = fmaf(k.z, fmaf(-e, S.z, wv), S.z);
            S.w = fmaf(k.w, fmaf(-e, S.w, wv), S.w);

            float dot = fmaf(S.x, q.x, S.y * q.y);
            dot = fmaf(S.z, q.z, dot);
            dot = fmaf(S.w, q.w, dot);
            dot += __shfl_xor_sync(0xffffffffu, dot, 8);
            dot += __shfl_xor_sync(0xffffffffu, dot, 4);
            dot += __shfl_xor_sync(0xffffffffu, dot, 2);
            dot += __shfl_xor_sync(0xffffffffu, dot, 1);

            float xc = fminf(fmaxf(dot, -9.0f), 9.0f);
            float ex = __expf(2.0f * xc);
            float o  = __fdividef(ex - 1.0f, ex + 1.0f);
            if (sub == 0) op[(size_t)(t + tt) * BN_] = o;
        }
    }

    *(float4*)(Sf + (size_t)b * 4096 + i * 64 + j0) = S;
}

// ---------------------------------------------------------------------------
extern "C" void kernel_launch(void* const* d_in, const int* in_sizes, int n_in,
                              void* d_out, int out_size)
{
    const float* x  = (const float*)d_in[0];
    const float* S0 = (const float*)d_in[1];
    const float* Wk = (const float*)d_in[2];
    const float* Wv = (const float*)d_in[3];
    const float* Wq = (const float*)d_in[4];
    const float* We = (const float*)d_in[5];
    const float* Ww = (const float*)d_in[6];

    float* out = (float*)d_out;            // [T,B,N]
    float* Sf  = out + TBN_;               // [B,N,N]

    cudaFuncSetAttribute(gates_kernel,
                         cudaFuncAttributeMaxDynamicSharedMemorySize, SMEM_BYTES);

    convw_kernel<<<320, 128>>>(Wk, Wq, We, Ww, Wv);
    gates_kernel<<<1024, 512, SMEM_BYTES>>>(x);
    scan_kernel<<<dim3(8, B_DIM), 128>>>(S0, out, Sf);
}

// round 6
// speedup vs baseline: 4.3099x; 1.2633x over previous
#include <cuda_runtime.h>
#include <cuda_bf16.h>
#include <math.h>

typedef unsigned int u32;

#define T_DIM 1024
#define B_DIM 64
#define D_DIM 512
#define N_DIM 64
#define BN_ (B_DIM * N_DIM)          /* 4096 */
#define TBN_ (T_DIM * BN_)           /* 4,194,304 */

// Scratch, padded by EIGHT timesteps for the scan's depth-7 circular prefetch
__device__ float g_k [TBN_ + 8 * BN_];
__device__ float g_q [TBN_ + 8 * BN_];
__device__ float g_e [TBN_ + 8 * BN_];
__device__ float g_wv[TBN_ + 8 * BN_];

// Concatenated weights, bf16 hi/lo split. Row order:
// [0:64)=Wk  [64:128)=Wq  [128:192)=We  [192:256)=Ww  [256:320)=Wv
__device__ __align__(16) __nv_bfloat16 g_Whi[320 * 512];
__device__ __align__(16) __nv_bfloat16 g_Wlo[320 * 512];

__device__ __forceinline__ float sigmoidf_(float x) {
    return 1.0f / (1.0f + __expf(-x));
}
__device__ __forceinline__ u32 pk(__nv_bfloat16 a, __nv_bfloat16 b) {
    __nv_bfloat162 t = __halves2bfloat162(a, b);   // .x = a = low 16 bits
    return *(u32*)&t;
}
__device__ __forceinline__ void cpasync16(void* s, const void* g) {
    u32 sa = (u32)__cvta_generic_to_shared(s);
    asm volatile("cp.async.cg.shared.global [%0], [%1], 16;\n" :: "r"(sa), "l"(g));
}
__device__ __forceinline__ void mma16816(float* d, const u32* a, const u32* b) {
    asm volatile(
        "mma.sync.aligned.m16n8k16.row.col.f32.bf16.bf16.f32 "
        "{%0,%1,%2,%3},{%4,%5,%6,%7},{%8,%9},{%0,%1,%2,%3};"
        : "+f"(d[0]), "+f"(d[1]), "+f"(d[2]), "+f"(d[3])
        : "r"(a[0]), "r"(a[1]), "r"(a[2]), "r"(a[3]), "r"(b[0]), "r"(b[1]));
}

// ---------------------------------------------------------------------------
// W conversion prepass: 5 x [64,512] f32 -> [320,512] bf16 hi/lo.
// ---------------------------------------------------------------------------
__global__ void convw_kernel(const float* __restrict__ Wk, const float* __restrict__ Wq,
                             const float* __restrict__ We, const float* __restrict__ Ww,
                             const float* __restrict__ Wv)
{
    const int row = blockIdx.x;          // 0..319
    const int tid = threadIdx.x;         // 0..127
    const float* src = (row < 64) ? Wk : (row < 128) ? Wq :
                       (row < 192) ? We : (row < 256) ? Ww : Wv;
    const int r = row & 63;
    float4 v = *(const float4*)(src + r * 512 + tid * 4);
    float vv[4] = {v.x, v.y, v.z, v.w};
    __nv_bfloat16 h[4], l[4];
    #pragma unroll
    for (int j = 0; j < 4; j++) {
        h[j] = __float2bfloat16(vv[j]);
        l[j] = __float2bfloat16(vv[j] - __bfloat162float(h[j]));
    }
    *(uint2*)(g_Whi + row * 512 + tid * 4) = make_uint2(pk(h[0], h[1]), pk(h[2], h[3]));
    *(uint2*)(g_Wlo + row * 512 + tid * 4) = make_uint2(pk(l[0], l[1]), pk(l[2], l[3]));
}

// ---------------------------------------------------------------------------
// Gates GEMM on tensor cores (bf16 3-split). grid 1024, block 512.
// (unchanged from R5 — 239us, HMMA-bound)
// ---------------------------------------------------------------------------
#define A_ELEMS (64 * 72)
#define B_ELEMS (320 * 72)
#define BBUF_ELEMS (2 * B_ELEMS)
#define SMEM_BYTES ((2 * A_ELEMS + 2 * BBUF_ELEMS) * 2)

__global__ __launch_bounds__(512, 1) void gates_kernel(const float* __restrict__ x)
{
    extern __shared__ char smem_raw[];
    __nv_bfloat16* Ahi = (__nv_bfloat16*)smem_raw;
    __nv_bfloat16* Alo = Ahi + A_ELEMS;
    __nv_bfloat16* Bb  = Alo + A_ELEMS;

    const int tid  = threadIdx.x;
    const int lane = tid & 31;
    const int warp = tid >> 5;
    const int wm = warp >> 3;
    const int wn = warp & 7;
    const int gid = lane >> 2;
    const int t4  = lane & 3;
    const int r0  = blockIdx.x * 64;

    float acc[2][5][4];
    #pragma unroll
    for (int mt = 0; mt < 2; mt++)
        #pragma unroll
        for (int nt = 0; nt < 5; nt++)
            #pragma unroll
            for (int c = 0; c < 4; c++) acc[mt][nt][c] = 0.f;

    const int a_row = tid >> 3;
    const int a_c8  = (tid & 7) * 8;
    const float* a_src = x + (size_t)(r0 + a_row) * 512 + a_c8;

    #pragma unroll
    for (int it = 0; it < 5; it++) {
        const int idx = tid + it * 512;
        const int row = idx >> 3, seg = idx & 7;
        cpasync16(Bb + row * 72 + seg * 8,            g_Whi + row * 512 + seg * 8);
        cpasync16(Bb + B_ELEMS + row * 72 + seg * 8,  g_Wlo + row * 512 + seg * 8);
    }
    asm volatile("cp.async.commit_group;");
    float4 xa0 = *(const float4*)(a_src);
    float4 xa1 = *(const float4*)(a_src + 4);

    for (int ct = 0; ct < 8; ct++) {
        __syncthreads();
        {
            float vv[8] = {xa0.x, xa0.y, xa0.z, xa0.w, xa1.x, xa1.y, xa1.z, xa1.w};
            __nv_bfloat16 h[8], l[8];
            #pragma unroll
            for (int j = 0; j < 8; j++) {
                h[j] = __float2bfloat16(vv[j]);
                l[j] = __float2bfloat16(vv[j] - __bfloat162float(h[j]));
            }
            *(uint4*)(Ahi + a_row * 72 + a_c8) =
                make_uint4(pk(h[0],h[1]), pk(h[2],h[3]), pk(h[4],h[5]), pk(h[6],h[7]));
            *(uint4*)(Alo + a_row * 72 + a_c8) =
                make_uint4(pk(l[0],l[1]), pk(l[2],l[3]), pk(l[4],l[5]), pk(l[6],l[7]));
        }
        if (ct < 7) {
            const int k0n = (ct + 1) * 64;
            __nv_bfloat16* Bn = Bb + ((ct + 1) & 1) * BBUF_ELEMS;
            #pragma unroll
            for (int it = 0; it < 5; it++) {
                const int idx = tid + it * 512;
                const int row = idx >> 3, seg = idx & 7;
                cpasync16(Bn + row * 72 + seg * 8,           g_Whi + row * 512 + k0n + seg * 8);
                cpasync16(Bn + B_ELEMS + row * 72 + seg * 8, g_Wlo + row * 512 + k0n + seg * 8);
            }
            asm volatile("cp.async.commit_group;");
            xa0 = *(const float4*)(a_src + k0n);
            xa1 = *(const float4*)(a_src + k0n + 4);
            asm volatile("cp.async.wait_group 1;");
        } else {
            asm volatile("cp.async.wait_group 0;");
        }
        __syncthreads();

        const __nv_bfloat16* Bhi = Bb + (ct & 1) * BBUF_ELEMS;
        const __nv_bfloat16* Blo = Bhi + B_ELEMS;

        #pragma unroll
        for (int ks = 0; ks < 4; ks++) {
            const int kc = ks * 16 + t4 * 2;
            u32 ah[2][4], al[2][4], bh[5][2], bl[5][2];
            #pragma unroll
            for (int mt = 0; mt < 2; mt++) {
                const int r1 = wm * 32 + mt * 16 + gid;
                ah[mt][0] = *(const u32*)(Ahi + r1 * 72 + kc);
                ah[mt][1] = *(const u32*)(Ahi + (r1 + 8) * 72 + kc);
                ah[mt][2] = *(const u32*)(Ahi + r1 * 72 + kc + 8);
                ah[mt][3] = *(const u32*)(Ahi + (r1 + 8) * 72 + kc + 8);
                al[mt][0] = *(const u32*)(Alo + r1 * 72 + kc);
                al[mt][1] = *(const u32*)(Alo + (r1 + 8) * 72 + kc);
                al[mt][2] = *(const u32*)(Alo + r1 * 72 + kc + 8);
                al[mt][3] = *(const u32*)(Alo + (r1 + 8) * 72 + kc + 8);
            }
            #pragma unroll
            for (int nt = 0; nt < 5; nt++) {
                const int n = wn * 40 + nt * 8 + gid;
                bh[nt][0] = *(const u32*)(Bhi + n * 72 + kc);
                bh[nt][1] = *(const u32*)(Bhi + n * 72 + kc + 8);
                bl[nt][0] = *(const u32*)(Blo + n * 72 + kc);
                bl[nt][1] = *(const u32*)(Blo + n * 72 + kc + 8);
            }
            #pragma unroll
            for (int mt = 0; mt < 2; mt++)
                #pragma unroll
                for (int nt = 0; nt < 5; nt++) mma16816(acc[mt][nt], ah[mt], bh[nt]);
            #pragma unroll
            for (int mt = 0; mt < 2; mt++)
                #pragma unroll
                for (int nt = 0; nt < 5; nt++) mma16816(acc[mt][nt], ah[mt], bl[nt]);
            #pragma unroll
            for (int mt = 0; mt < 2; mt++)
                #pragma unroll
                for (int nt = 0; nt < 5; nt++) mma16816(acc[mt][nt], al[mt], bh[nt]);
        }
    }

    float* Ls = (float*)smem_raw;
    __syncthreads();
    #pragma unroll
    for (int mt = 0; mt < 2; mt++) {
        const int row1 = wm * 32 + mt * 16 + gid;
        #pragma unroll
        for (int nt = 0; nt < 5; nt++) {
            const int col = wn * 40 + nt * 8 + t4 * 2;
            *(float2*)(Ls + row1 * 328 + col)       = make_float2(acc[mt][nt][0], acc[mt][nt][1]);
            *(float2*)(Ls + (row1 + 8) * 328 + col) = make_float2(acc[mt][nt][2], acc[mt][nt][3]);
        }
    }
    __syncthreads();

    if (tid < 256) {
        const int gate = tid >> 7;
        const int row  = (tid >> 1) & 63;
        const int part = tid & 1;
        const float* rp = Ls + row * 328 + gate * 64 + part * 32;
        float v[32];
        #pragma unroll
        for (int c = 0; c < 32; c += 4) {
            float4 t4v = *(const float4*)(rp + c);
            v[c] = t4v.x; v[c+1] = t4v.y; v[c+2] = t4v.z; v[c+3] = t4v.w;
        }
        float m = v[0];
        #pragma unroll
        for (int c = 1; c < 32; c++) m = fmaxf(m, v[c]);
        m = fmaxf(m, __shfl_xor_sync(0xffffffffu, m, 1));
        float s = 0.f;
        #pragma unroll
        for (int c = 0; c < 32; c++) { v[c] = __expf(v[c] - m); s += v[c]; }
        s += __shfl_xor_sync(0xffffffffu, s, 1);
        const float inv = 1.0f / s;
        float* dst = ((gate == 0) ? g_k : g_q) + (size_t)(r0 + row) * 64 + part * 32;
        #pragma unroll
        for (int c = 0; c < 32; c += 4)
            *(float4*)(dst + c) = make_float4(v[c]*inv, v[c+1]*inv, v[c+2]*inv, v[c+3]*inv);
    } else {
        const int t2 = tid - 256;
        for (int i4 = t2; i4 < 1024; i4 += 256) {
            const int rr = i4 >> 4, c4 = (i4 & 15) * 4;
            float4 a = *(const float4*)(Ls + rr * 328 + 128 + c4);
            *(float4*)(g_e + (size_t)(r0 + rr) * 64 + c4) =
                make_float4(sigmoidf_(a.x), sigmoidf_(a.y), sigmoidf_(a.z), sigmoidf_(a.w));
        }
        for (int i4 = t2; i4 < 1024; i4 += 256) {
            const int rr = i4 >> 4, c4 = (i4 & 15) * 4;
            float4 w = *(const float4*)(Ls + rr * 328 + 192 + c4);
            float4 vv = *(const float4*)(Ls + rr * 328 + 256 + c4);
            *(float4*)(g_wv + (size_t)(r0 + rr) * 64 + c4) =
                make_float4(sigmoidf_(w.x)*vv.x, sigmoidf_(w.y)*vv.y,
                            sigmoidf_(w.z)*vv.z, sigmoidf_(w.w)*vv.w);
        }
    }
}

// ---------------------------------------------------------------------------
// Scan: 2 rows per warp, depth-7 circular register prefetch (ring of 8),
// t-loop unrolled x8.
// ---------------------------------------------------------------------------
__global__ __launch_bounds__(128) void scan_kernel(
    const float* __restrict__ S0,
    float* __restrict__ out,
    float* __restrict__ Sf)
{
    const int b    = blockIdx.y;
    const int warp = threadIdx.x >> 5;
    const int lane = threadIdx.x & 31;
    const int half = lane >> 4;
    const int sub  = lane & 15;
    const int i    = blockIdx.x * 8 + warp * 2 + half;
    const int j0   = sub * 4;

    float4 S = *(const float4*)(S0 + (size_t)b * 4096 + i * 64 + j0);

    const float* kp  = g_k  + b * 64 + j0;
    const float* qp  = g_q  + b * 64 + j0;
    const float* ep  = g_e  + b * 64 + i;
    const float* wvp = g_wv + b * 64 + i;
    float*       op  = out  + b * 64 + i;

    float4 kb[8], qb[8];
    float  eb[8], wb[8];
    #pragma unroll
    for (int s = 0; s < 7; s++) {               // prologue: t = 0..6
        kb[s] = *(const float4*)(kp + s * BN_);
        qb[s] = *(const float4*)(qp + s * BN_);
        eb[s] = ep[s * BN_];
        wb[s] = wvp[s * BN_];
    }

    for (int t = 0; t < T_DIM; t += 8) {
        #pragma unroll
        for (int tt = 0; tt < 8; tt++) {
            const int cur = tt;                  // (t+tt)&7 == tt since t%8==0
            const int nxt = (tt + 7) & 7;
            const int off = (t + tt + 7) * BN_;  // padded +8, safe at end
            kb[nxt] = *(const float4*)(kp + off);
            qb[nxt] = *(const float4*)(qp + off);
            eb[nxt] = ep[off];
            wb[nxt] = wvp[off];

            const float e = eb[cur], wv = wb[cur];
            const float4 k = kb[cur], q = qb[cur];

            S.x = fmaf(k.x, fmaf(-e, S.x, wv), S.x);
            S.y = fmaf(k.y, fmaf(-e, S.y, wv), S.y);
            S.z = fmaf(k.z, fmaf(-e, S.z, wv), S.z);
            S.w = fmaf(k.w, fmaf(-e, S.w, wv), S.w);

            float dot = fmaf(S.x, q.x, S.y * q.y);
            dot = fmaf(S.z, q.z, dot);
            dot = fmaf(S.w, q.w, dot);
            dot += __shfl_xor_sync(0xffffffffu, dot, 8);
            dot += __shfl_xor_sync(0xffffffffu, dot, 4);
            dot += __shfl_xor_sync(0xffffffffu, dot, 2);
            dot += __shfl_xor_sync(0xffffffffu, dot, 1);

            float xc = fminf(fmaxf(dot, -9.0f), 9.0f);
            float ex = __expf(2.0f * xc);
            float o  = __fdividef(ex - 1.0f, ex + 1.0f);
            if (sub == 0) op[(size_t)(t + tt) * BN_] = o;
        }
    }

    *(float4*)(Sf + (size_t)b * 4096 + i * 64 + j0) = S;
}

// ---------------------------------------------------------------------------
extern "C" void kernel_launch(void* const* d_in, const int* in_sizes, int n_in,
                              void* d_out, int out_size)
{
    const float* x  = (const float*)d_in[0];
    const float* S0 = (const float*)d_in[1];
    const float* Wk = (const float*)d_in[2];
    const float* Wv = (const float*)d_in[3];
    const float* Wq = (const float*)d_in[4];
    const float* We = (const float*)d_in[5];
    const float* Ww = (const float*)d_in[6];

    float* out = (float*)d_out;            // [T,B,N]
    float* Sf  = out + TBN_;               // [B,N,N]

    cudaFuncSetAttribute(gates_kernel,
                         cudaFuncAttributeMaxDynamicSharedMemorySize, SMEM_BYTES);

    convw_kernel<<<320, 128>>>(Wk, Wq, We, Ww, Wv);
    gates_kernel<<<1024, 512, SMEM_BYTES>>>(x);
    scan_kernel<<<dim3(8, B_DIM), 128>>>(S0, out, Sf);
}

// round 8
// speedup vs baseline: 4.3519x; 1.0097x over previous
#include <cuda_runtime.h>
#include <cuda_bf16.h>
#include <math.h>

typedef unsigned int u32;

#define T_DIM 1024
#define B_DIM 64
#define D_DIM 512
#define N_DIM 64
#define BN_ (B_DIM * N_DIM)          /* 4096 */
#define TBN_ (T_DIM * BN_)           /* 4,194,304 */

// Scratch, padded by EIGHT timesteps for the scan's depth-7 circular prefetch
__device__ float g_k [TBN_ + 8 * BN_];
__device__ float g_q [TBN_ + 8 * BN_];
__device__ float g_e [TBN_ + 8 * BN_];
__device__ float g_wv[TBN_ + 8 * BN_];

// Concatenated weights, bf16 hi/lo split. Row order:
// [0:64)=Wk  [64:128)=Wq  [128:192)=We  [192:256)=Ww  [256:320)=Wv
__device__ __align__(16) __nv_bfloat16 g_Whi[320 * 512];
__device__ __align__(16) __nv_bfloat16 g_Wlo[320 * 512];

__device__ __forceinline__ float sigmoidf_(float x) {
    return 1.0f / (1.0f + __expf(-x));
}
__device__ __forceinline__ u32 pk(__nv_bfloat16 a, __nv_bfloat16 b) {
    __nv_bfloat162 t = __halves2bfloat162(a, b);   // .x = a = low 16 bits
    return *(u32*)&t;
}
__device__ __forceinline__ void cpasync16(void* s, const void* g) {
    u32 sa = (u32)__cvta_generic_to_shared(s);
    asm volatile("cp.async.cg.shared.global [%0], [%1], 16;\n" :: "r"(sa), "l"(g));
}
__device__ __forceinline__ void mma16816(float* d, const u32* a, const u32* b) {
    asm volatile(
        "mma.sync.aligned.m16n8k16.row.col.f32.bf16.bf16.f32 "
        "{%0,%1,%2,%3},{%4,%5,%6,%7},{%8,%9},{%0,%1,%2,%3};"
        : "+f"(d[0]), "+f"(d[1]), "+f"(d[2]), "+f"(d[3])
        : "r"(a[0]), "r"(a[1]), "r"(a[2]), "r"(a[3]), "r"(b[0]), "r"(b[1]));
}
__device__ __forceinline__ void ldsm_x4(u32* r, u32 saddr) {
    asm volatile("ldmatrix.sync.aligned.m8n8.x4.shared.b16 {%0,%1,%2,%3}, [%4];"
        : "=r"(r[0]), "=r"(r[1]), "=r"(r[2]), "=r"(r[3]) : "r"(saddr));
}
__device__ __forceinline__ void ldsm_x2(u32* r, u32 saddr) {
    asm volatile("ldmatrix.sync.aligned.m8n8.x2.shared.b16 {%0,%1}, [%2];"
        : "=r"(r[0]), "=r"(r[1]) : "r"(saddr));
}

// ---------------------------------------------------------------------------
// W conversion prepass: 5 x [64,512] f32 -> [320,512] bf16 hi/lo.
// ---------------------------------------------------------------------------
__global__ void convw_kernel(const float* __restrict__ Wk, const float* __restrict__ Wq,
                             const float* __restrict__ We, const float* __restrict__ Ww,
                             const float* __restrict__ Wv)
{
    const int row = blockIdx.x;          // 0..319
    const int tid = threadIdx.x;         // 0..127
    const float* src = (row < 64) ? Wk : (row < 128) ? Wq :
                       (row < 192) ? We : (row < 256) ? Ww : Wv;
    const int r = row & 63;
    float4 v = *(const float4*)(src + r * 512 + tid * 4);
    float vv[4] = {v.x, v.y, v.z, v.w};
    __nv_bfloat16 h[4], l[4];
    #pragma unroll
    for (int j = 0; j < 4; j++) {
        h[j] = __float2bfloat16(vv[j]);
        l[j] = __float2bfloat16(vv[j] - __bfloat162float(h[j]));
    }
    *(uint2*)(g_Whi + row * 512 + tid * 4) = make_uint2(pk(h[0], h[1]), pk(h[2], h[3]));
    *(uint2*)(g_Wlo + row * 512 + tid * 4) = make_uint2(pk(l[0], l[1]), pk(l[2], l[3]));
}

// ---------------------------------------------------------------------------
// Gates GEMM on tensor cores (bf16 3-split), ldmatrix fragment loads.
// grid 1024, block 512. CTA: 64 rows x 320 cols, K=512 in 8 chunks of 64.
// smem: A hi/lo [64][72], B hi/lo [320][72] x2 (cp.async double buffer).
// Warp (16): wm = warp>>3 (2), wn = warp&7 (8); warp tile 32 x 40.
// ---------------------------------------------------------------------------
#define A_ELEMS (64 * 72)
#define B_ELEMS (320 * 72)
#define BBUF_ELEMS (2 * B_ELEMS)
#define SMEM_BYTES ((2 * A_ELEMS + 2 * BBUF_ELEMS) * 2)

__global__ __launch_bounds__(512, 1) void gates_kernel(const float* __restrict__ x)
{
    extern __shared__ char smem_raw[];
    __nv_bfloat16* Ahi = (__nv_bfloat16*)smem_raw;
    __nv_bfloat16* Alo = Ahi + A_ELEMS;
    __nv_bfloat16* Bb  = Alo + A_ELEMS;

    const int tid  = threadIdx.x;
    const int lane = tid & 31;
    const int warp = tid >> 5;
    const int wm = warp >> 3;
    const int wn = warp & 7;
    const int gid = lane >> 2;
    const int t4  = lane & 3;
    const int r0  = blockIdx.x * 64;

    float acc[2][5][4];
    #pragma unroll
    for (int mt = 0; mt < 2; mt++)
        #pragma unroll
        for (int nt = 0; nt < 5; nt++)
            #pragma unroll
            for (int c = 0; c < 4; c++) acc[mt][nt][c] = 0.f;

    const int a_row = tid >> 3;
    const int a_c8  = (tid & 7) * 8;
    const float* a_src = x + (size_t)(r0 + a_row) * 512 + a_c8;

    // lane-invariant ldmatrix byte offsets (stride 72 elems = 144 B)
    // A x4: row = wm*32 + mt*16 + (lane&15), koff = (lane>>4)*8
    const u32 inv_a = (u32)(((lane & 15) * 72 + (lane >> 4) * 8) * 2);
    // B x4 pair: n = p*16 + (lane>>4)*8 + (lane&7), koff = ((lane>>3)&1)*8
    const u32 inv_b = (u32)((((lane >> 4) * 8 + (lane & 7)) * 72 + ((lane >> 3) & 1) * 8) * 2);
    // B x2 tail: n = 32 + (lane&7), koff = ((lane>>3)&1)*8   (lanes 0-15 used)
    const u32 inv_b2 = (u32)(((lane & 7) * 72 + ((lane >> 3) & 1) * 8) * 2);

    const u32 sAhi = (u32)__cvta_generic_to_shared(Ahi) + (u32)(wm * 32 * 144) + inv_a;
    const u32 sAlo = sAhi + (u32)(A_ELEMS * 2);
    const u32 sB   = (u32)__cvta_generic_to_shared(Bb);
    const u32 bRow = (u32)(wn * 40 * 144);         // warp's B base (bytes)

    // --- prologue: B chunk 0 via cp.async, A chunk 0 into regs ---
    #pragma unroll
    for (int it = 0; it < 5; it++) {
        const int idx = tid + it * 512;
        const int row = idx >> 3, seg = idx & 7;
        cpasync16(Bb + row * 72 + seg * 8,            g_Whi + row * 512 + seg * 8);
        cpasync16(Bb + B_ELEMS + row * 72 + seg * 8,  g_Wlo + row * 512 + seg * 8);
    }
    asm volatile("cp.async.commit_group;");
    float4 xa0 = *(const float4*)(a_src);
    float4 xa1 = *(const float4*)(a_src + 4);

    for (int ct = 0; ct < 8; ct++) {
        __syncthreads();
        {
            float vv[8] = {xa0.x, xa0.y, xa0.z, xa0.w, xa1.x, xa1.y, xa1.z, xa1.w};
            __nv_bfloat16 h[8], l[8];
            #pragma unroll
            for (int j = 0; j < 8; j++) {
                h[j] = __float2bfloat16(vv[j]);
                l[j] = __float2bfloat16(vv[j] - __bfloat162float(h[j]));
            }
            *(uint4*)(Ahi + a_row * 72 + a_c8) =
                make_uint4(pk(h[0],h[1]), pk(h[2],h[3]), pk(h[4],h[5]), pk(h[6],h[7]));
            *(uint4*)(Alo + a_row * 72 + a_c8) =
                make_uint4(pk(l[0],l[1]), pk(l[2],l[3]), pk(l[4],l[5]), pk(l[6],l[7]));
        }
        if (ct < 7) {
            const int k0n = (ct + 1) * 64;
            __nv_bfloat16* Bn = Bb + ((ct + 1) & 1) * BBUF_ELEMS;
            #pragma unroll
            for (int it = 0; it < 5; it++) {
                const int idx = tid + it * 512;
                const int row = idx >> 3, seg = idx & 7;
                cpasync16(Bn + row * 72 + seg * 8,           g_Whi + row * 512 + k0n + seg * 8);
                cpasync16(Bn + B_ELEMS + row * 72 + seg * 8, g_Wlo + row * 512 + k0n + seg * 8);
            }
            asm volatile("cp.async.commit_group;");
            xa0 = *(const float4*)(a_src + k0n);
            xa1 = *(const float4*)(a_src + k0n + 4);
            asm volatile("cp.async.wait_group 1;");
        } else {
            asm volatile("cp.async.wait_group 0;");
        }
        __syncthreads();

        const u32 sBhi = sB + (u32)((ct & 1) * BBUF_ELEMS * 2) + bRow;
        const u32 sBlo = sBhi + (u32)(B_ELEMS * 2);

        #pragma unroll
        for (int ks = 0; ks < 4; ks++) {
            const u32 kb = (u32)(ks * 32);        // 16 elems * 2B
            u32 ah[2][4], al[2][4], bh[5][2], bl[5][2];
            // A fragments: 4 x ldmatrix.x4
            ldsm_x4(ah[0], sAhi + kb);
            ldsm_x4(ah[1], sAhi + 16 * 144 + kb);
            ldsm_x4(al[0], sAlo + kb);
            ldsm_x4(al[1], sAlo + 16 * 144 + kb);
            // B fragments: 2 x4 + 1 x2 per hi/lo
            ldsm_x4(bh[0], sBhi + inv_b + kb);                 // nt0, nt1
            ldsm_x4(bh[2], sBhi + 16 * 144 + inv_b + kb);      // nt2, nt3
            ldsm_x2(bh[4], sBhi + 32 * 144 + inv_b2 + kb);     // nt4
            ldsm_x4(bl[0], sBlo + inv_b + kb);
            ldsm_x4(bl[2], sBlo + 16 * 144 + inv_b + kb);
            ldsm_x2(bl[4], sBlo + 32 * 144 + inv_b2 + kb);

            #pragma unroll
            for (int mt = 0; mt < 2; mt++)
                #pragma unroll
                for (int nt = 0; nt < 5; nt++) mma16816(acc[mt][nt], ah[mt], bh[nt]);
            #pragma unroll
            for (int mt = 0; mt < 2; mt++)
                #pragma unroll
                for (int nt = 0; nt < 5; nt++) mma16816(acc[mt][nt], ah[mt], bl[nt]);
            #pragma unroll
            for (int mt = 0; mt < 2; mt++)
                #pragma unroll
                for (int nt = 0; nt < 5; nt++) mma16816(acc[mt][nt], al[mt], bh[nt]);
        }
    }

    // ---- epilogue: stage D[64][320] to smem (stride 328), fuse activations ----
    float* Ls = (float*)smem_raw;
    __syncthreads();
    #pragma unroll
    for (int mt = 0; mt < 2; mt++) {
        const int row1 = wm * 32 + mt * 16 + gid;
        #pragma unroll
        for (int nt = 0; nt < 5; nt++) {
            const int col = wn * 40 + nt * 8 + t4 * 2;
            *(float2*)(Ls + row1 * 328 + col)       = make_float2(acc[mt][nt][0], acc[mt][nt][1]);
            *(float2*)(Ls + (row1 + 8) * 328 + col) = make_float2(acc[mt][nt][2], acc[mt][nt][3]);
        }
    }
    __syncthreads();

    if (tid < 256) {
        const int gate = tid >> 7;            // 0=k, 1=q
        const int row  = (tid >> 1) & 63;
        const int part = tid & 1;
        const float* rp = Ls + row * 328 + gate * 64 + part * 32;
        float v[32];
        #pragma unroll
        for (int c = 0; c < 32; c += 4) {
            float4 t4v = *(const float4*)(rp + c);
            v[c] = t4v.x; v[c+1] = t4v.y; v[c+2] = t4v.z; v[c+3] = t4v.w;
        }
        float m = v[0];
        #pragma unroll
        for (int c = 1; c < 32; c++) m = fmaxf(m, v[c]);
        m = fmaxf(m, __shfl_xor_sync(0xffffffffu, m, 1));
        float s = 0.f;
        #pragma unroll
        for (int c = 0; c < 32; c++) { v[c] = __expf(v[c] - m); s += v[c]; }
        s += __shfl_xor_sync(0xffffffffu, s, 1);
        const float inv = 1.0f / s;
        float* dst = ((gate == 0) ? g_k : g_q) + (size_t)(r0 + row) * 64 + part * 32;
        #pragma unroll
        for (int c = 0; c < 32; c += 4)
            *(float4*)(dst + c) = make_float4(v[c]*inv, v[c+1]*inv, v[c+2]*inv, v[c+3]*inv);
    } else {
        const int t2 = tid - 256;
        for (int i4 = t2; i4 < 1024; i4 += 256) {
            const int rr = i4 >> 4, c4 = (i4 & 15) * 4;
            float4 a = *(const float4*)(Ls + rr * 328 + 128 + c4);
            *(float4*)(g_e + (size_t)(r0 + rr) * 64 + c4) =
                make_float4(sigmoidf_(a.x), sigmoidf_(a.y), sigmoidf_(a.z), sigmoidf_(a.w));
        }
        for (int i4 = t2; i4 < 1024; i4 += 256) {
            const int rr = i4 >> 4, c4 = (i4 & 15) * 4;
            float4 w = *(const float4*)(Ls + rr * 328 + 192 + c4);
            float4 vv = *(const float4*)(Ls + rr * 328 + 256 + c4);
            *(float4*)(g_wv + (size_t)(r0 + rr) * 64 + c4) =
                make_float4(sigmoidf_(w.x)*vv.x, sigmoidf_(w.y)*vv.y,
                            sigmoidf_(w.z)*vv.z, sigmoidf_(w.w)*vv.w);
        }
    }
}

// ---------------------------------------------------------------------------
// Scan: 2 rows per warp, depth-7 circular register prefetch (unchanged R6).
// ---------------------------------------------------------------------------
__global__ __launch_bounds__(128) void scan_kernel(
    const float* __restrict__ S0,
    float* __restrict__ out,
    float* __restrict__ Sf)
{
    const int b    = blockIdx.y;
    const int warp = threadIdx.x >> 5;
    const int lane = threadIdx.x & 31;
    const int half = lane >> 4;
    const int sub  = lane & 15;
    const int i    = blockIdx.x * 8 + warp * 2 + half;
    const int j0   = sub * 4;

    float4 S = *(const float4*)(S0 + (size_t)b * 4096 + i * 64 + j0);

    const float* kp  = g_k  + b * 64 + j0;
    const float* qp  = g_q  + b * 64 + j0;
    const float* ep  = g_e  + b * 64 + i;
    const float* wvp = g_wv + b * 64 + i;
    float*       op  = out  + b * 64 + i;

    float4 kb[8], qb[8];
    float  eb[8], wb[8];
    #pragma unroll
    for (int s = 0; s < 7; s++) {
        kb[s] = *(const float4*)(kp + s * BN_);
        qb[s] = *(const float4*)(qp + s * BN_);
        eb[s] = ep[s * BN_];
        wb[s] = wvp[s * BN_];
    }

    for (int t = 0; t < T_DIM; t += 8) {
        #pragma unroll
        for (int tt = 0; tt < 8; tt++) {
            const int cur = tt;
            const int nxt = (tt + 7) & 7;
            const int off = (t + tt + 7) * BN_;
            kb[nxt] = *(const float4*)(kp + off);
            qb[nxt] = *(const float4*)(qp + off);
            eb[nxt] = ep[off];
            wb[nxt] = wvp[off];

            const float e = eb[cur], wv = wb[cur];
            const float4 k = kb[cur], q = qb[cur];

            S.x = fmaf(k.x, fmaf(-e, S.x, wv), S.x);
            S.y = fmaf(k.y, fmaf(-e, S.y, wv), S.y);
            S.z = fmaf(k.z, fmaf(-e, S.z, wv), S.z);
            S.w = fmaf(k.w, fmaf(-e, S.w, wv), S.w);

            float dot = fmaf(S.x, q.x, S.y * q.y);
            dot = fmaf(S.z, q.z, dot);
            dot = fmaf(S.w, q.w, dot);
            dot += __shfl_xor_sync(0xffffffffu, dot, 8);
            dot += __shfl_xor_sync(0xffffffffu, dot, 4);
            dot += __shfl_xor_sync(0xffffffffu, dot, 2);
            dot += __shfl_xor_sync(0xffffffffu, dot, 1);

            float xc = fminf(fmaxf(dot, -9.0f), 9.0f);
            float ex = __expf(2.0f * xc);
            float o  = __fdividef(ex - 1.0f, ex + 1.0f);
            if (sub == 0) op[(size_t)(t + tt) * BN_] = o;
        }
    }

    *(float4*)(Sf + (size_t)b * 4096 + i * 64 + j0) = S;
}

// ---------------------------------------------------------------------------
extern "C" void kernel_launch(void* const* d_in, const int* in_sizes, int n_in,
                              void* d_out, int out_size)
{
    const float* x  = (const float*)d_in[0];
    const float* S0 = (const float*)d_in[1];
    const float* Wk = (const float*)d_in[2];
    const float* Wv = (const float*)d_in[3];
    const float* Wq = (const float*)d_in[4];
    const float* We = (const float*)d_in[5];
    const float* Ww = (const float*)d_in[6];

    float* out = (float*)d_out;            // [T,B,N]
    float* Sf  = out + TBN_;               // [B,N,N]

    cudaFuncSetAttribute(gates_kernel,
                         cudaFuncAttributeMaxDynamicSharedMemorySize, SMEM_BYTES);

    convw_kernel<<<320, 128>>>(Wk, Wq, We, Ww, Wv);
    gates_kernel<<<1024, 512, SMEM_BYTES>>>(x);
    scan_kernel<<<dim3(8, B_DIM), 128>>>(S0, out, Sf);
}